// round 15
// baseline (speedup 1.0000x reference)
#include <cuda_runtime.h>
#include <cuda_fp16.h>
#include <cstddef>
#include <cstdint>

#define N_NODES 50000
#define N_EDGES 1600000
#define INDIM   256
#define HIDIM   128
#define OUTDIM  64
#define NB_SCAN ((N_NODES + 256) / 256)   // 196

// ---------------- scratch (allocation-free: __device__ globals) ----------------
__device__ int            g_degi  [N_NODES];
__device__ unsigned short g_pos   [N_EDGES];   // slot within dst bucket (coalesced)
__device__ int            g_rowptr[N_NODES + 1];
__device__ int            g_csr   [N_EDGES];   // int: 4B scatter granularity
__device__ unsigned long long g_desc[NB_SCAN];
__device__ float  g_dinv  [N_NODES];
__device__ __half g_wt1   [(size_t)HIDIM * INDIM];     // W1^T fp16 [128][256]
__device__ __half g_wt2   [(size_t)OUTDIM * HIDIM];    // W2^T fp16 [64][128]
__device__ __half g_u1h   [(size_t)N_NODES * HIDIM];   // x @ W1, then dinv-scaled
__device__ __half g_h     [(size_t)N_NODES * HIDIM];   // layer1 out (fp16)
__device__ __half g_u2h   [(size_t)N_NODES * OUTDIM];  // dinv * (h @ W2) (fp16)

// ---------------- weight convert kernels (split) ----------------
__global__ void conv_wt1(const float* __restrict__ W1, __half* __restrict__ Wt1) {
    int i = blockIdx.x * blockDim.x + threadIdx.x;
    if (i < INDIM * HIDIM) {
        int m = i / INDIM, k = i % INDIM;
        Wt1[i] = __float2half(W1[(size_t)k * HIDIM + m]);
    }
}
__global__ void conv_wt2(const float* __restrict__ W2, __half* __restrict__ Wt2) {
    int i = blockIdx.x * blockDim.x + threadIdx.x;
    if (i < HIDIM * OUTDIM) {
        int m = i / HIDIM, k = i % HIDIM;
        Wt2[i] = __float2half(W2[(size_t)k * OUTDIM + m]);
    }
}

// ---------------- CSR build kernels ----------------
__global__ void deg_pos4(const int4* __restrict__ col4, int* __restrict__ degi,
                         ushort4* __restrict__ pos4) {
    int i = blockIdx.x * blockDim.x + threadIdx.x;
    if (i >= N_EDGES / 4) return;
    int4 c = col4[i];
    ushort4 p;
    p.x = (unsigned short)atomicAdd(&degi[c.x], 1);
    p.y = (unsigned short)atomicAdd(&degi[c.y], 1);
    p.z = (unsigned short)atomicAdd(&degi[c.z], 1);
    p.w = (unsigned short)atomicAdd(&degi[c.w], 1);
    pos4[i] = p;
}

__global__ void scan_rowptr(const int* __restrict__ degi, float* __restrict__ dinv,
                            int* __restrict__ rowptr,
                            volatile unsigned long long* desc)
{
    __shared__ int sh[256];
    __shared__ int red[256];
    const int b = blockIdx.x, t = threadIdx.x;
    const int i = b * 256 + t;

    int v = (i < N_NODES) ? degi[i] : 0;
    if (i < N_NODES) dinv[i] = rsqrtf((float)v + 1.0f);   // +1 self loop

    sh[t] = v;
    __syncthreads();
    #pragma unroll
    for (int off = 1; off < 256; off <<= 1) {
        int x = (t >= off) ? sh[t - off] : 0;
        __syncthreads();
        sh[t] += x;
        __syncthreads();
    }
    const int incl  = sh[t];
    const int total = sh[255];

    if (t == 0) desc[b] = (1ULL << 32) | (unsigned)total;

    int contrib = 0;
    if (t < b) {
        unsigned long long d;
        do { d = desc[t]; } while ((d >> 32) == 0ULL);
        contrib = (int)(unsigned)d;
    }
    red[t] = contrib;
    __syncthreads();
    #pragma unroll
    for (int s = 128; s > 0; s >>= 1) {
        if (t < s) red[t] += red[t + s];
        __syncthreads();
    }
    const int off = red[0];

    if (i <= N_NODES) rowptr[i] = off + incl - v;
}

__global__ void csr_fill4(const int4* __restrict__ row4, const int4* __restrict__ col4,
                          const ushort4* __restrict__ pos4,
                          const int* __restrict__ rowptr, int* __restrict__ csr) {
    int i = blockIdx.x * blockDim.x + threadIdx.x;
    if (i >= N_EDGES / 4) return;
    int4 r = row4[i];
    int4 c = col4[i];
    ushort4 p = pos4[i];
    int b0 = __ldg(&rowptr[c.x]);
    int b1 = __ldg(&rowptr[c.y]);
    int b2 = __ldg(&rowptr[c.z]);
    int b3 = __ldg(&rowptr[c.w]);
    csr[b0 + p.x] = r.x;
    csr[b1 + p.y] = r.y;
    csr[b2 + p.z] = r.z;
    csr[b3 + p.w] = r.w;
}

// ---------------- scale messages: g[row,:] *= dinv[row]  (fp16, in place) -----
__global__ void scale_g(__half* __restrict__ G, const float* __restrict__ dinv) {
    size_t i = (size_t)blockIdx.x * blockDim.x + threadIdx.x;
    constexpr size_t N8 = (size_t)N_NODES * HIDIM / 8;   // uint4 = 8 halves
    if (i >= N8) return;
    int row = (int)(i / (HIDIM / 8));
    float s = dinv[row];
    uint4 raw = reinterpret_cast<uint4*>(G)[i];
    __half2 p0 = *reinterpret_cast<__half2*>(&raw.x);
    __half2 p1 = *reinterpret_cast<__half2*>(&raw.y);
    __half2 p2 = *reinterpret_cast<__half2*>(&raw.z);
    __half2 p3 = *reinterpret_cast<__half2*>(&raw.w);
    float2 f0 = __half22float2(p0), f1 = __half22float2(p1);
    float2 f2 = __half22float2(p2), f3 = __half22float2(p3);
    p0 = __floats2half2_rn(f0.x * s, f0.y * s);
    p1 = __floats2half2_rn(f1.x * s, f1.y * s);
    p2 = __floats2half2_rn(f2.x * s, f2.y * s);
    p3 = __floats2half2_rn(f3.x * s, f3.y * s);
    raw.x = *reinterpret_cast<unsigned*>(&p0);
    raw.y = *reinterpret_cast<unsigned*>(&p1);
    raw.z = *reinterpret_cast<unsigned*>(&p2);
    raw.w = *reinterpret_cast<unsigned*>(&p3);
    reinterpret_cast<uint4*>(G)[i] = raw;
}

// ---------------- tensor-core fp16 GEMM: out = [dinv⊙](A @ Bt^T) ----------------
__device__ __forceinline__ void mma16816(float* c, const unsigned* a,
                                         unsigned b0, unsigned b1) {
    asm volatile(
        "mma.sync.aligned.m16n8k16.row.col.f32.f16.f16.f32 "
        "{%0,%1,%2,%3}, {%4,%5,%6,%7}, {%8,%9}, {%0,%1,%2,%3};"
        : "+f"(c[0]), "+f"(c[1]), "+f"(c[2]), "+f"(c[3])
        : "r"(a[0]), "r"(a[1]), "r"(a[2]), "r"(a[3]), "r"(b0), "r"(b1));
}

template <int K, int BN, bool AF32, bool DSCALE>
__global__ void __launch_bounds__(256)
gemm_mma(const void* __restrict__ Av, const __half* __restrict__ Bt,
         __half* __restrict__ out, int n, const float* __restrict__ dsc)
{
    constexpr int BM  = 128;
    constexpr int BK  = 32;
    constexpr int PAD = 40;
    constexpr int WN  = BN / 2;
    constexpr int NT  = WN / 8;
    constexpr int AL  = (BM * 8) / 256;
    constexpr int BL  = (BN * 8) / 256;

    __shared__ __half As[2][BM][PAD];
    __shared__ __half Bs[2][BN][PAD];

    const int tid  = threadIdx.x;
    const int lane = tid & 31;
    const int wid  = tid >> 5;
    const int wr   = wid & 3;
    const int wc   = wid >> 2;
    const int rowBase = blockIdx.x * BM;

    const int r4 = lane >> 2;
    const int c2 = (lane & 3) * 2;

    float acc[2][NT][4];
    #pragma unroll
    for (int mt = 0; mt < 2; mt++)
        #pragma unroll
        for (int nt = 0; nt < NT; nt++)
            #pragma unroll
            for (int q = 0; q < 4; q++) acc[mt][nt][q] = 0.f;

    uint2 abuf[AL], bbuf[BL];

    auto loadA = [&](int k0) {
        #pragma unroll
        for (int i = 0; i < AL; i++) {
            int idx = tid + i * 256;
            int r = idx >> 3, sg = idx & 7;
            int gr = rowBase + r;
            uint2 v = make_uint2(0u, 0u);
            if (gr < n) {
                if (AF32) {
                    float4 f = *reinterpret_cast<const float4*>(
                        (const float*)Av + (size_t)gr * K + k0 + sg * 4);
                    __half2 h0 = __floats2half2_rn(f.x, f.y);
                    __half2 h1 = __floats2half2_rn(f.z, f.w);
                    v.x = *reinterpret_cast<unsigned*>(&h0);
                    v.y = *reinterpret_cast<unsigned*>(&h1);
                } else {
                    v = *reinterpret_cast<const uint2*>(
                        (const __half*)Av + (size_t)gr * K + k0 + sg * 4);
                }
            }
            abuf[i] = v;
        }
    };
    auto loadB = [&](int k0) {
        #pragma unroll
        for (int i = 0; i < BL; i++) {
            int idx = tid + i * 256;
            int r = idx >> 3, sg = idx & 7;
            bbuf[i] = *reinterpret_cast<const uint2*>(&Bt[(size_t)r * K + k0 + sg * 4]);
        }
    };
    auto store = [&](int s) {
        #pragma unroll
        for (int i = 0; i < AL; i++) {
            int idx = tid + i * 256;
            int r = idx >> 3, sg = idx & 7;
            *reinterpret_cast<uint2*>(&As[s][r][sg * 4]) = abuf[i];
        }
        #pragma unroll
        for (int i = 0; i < BL; i++) {
            int idx = tid + i * 256;
            int r = idx >> 3, sg = idx & 7;
            *reinterpret_cast<uint2*>(&Bs[s][r][sg * 4]) = bbuf[i];
        }
    };

    loadA(0); loadB(0);
    store(0);
    __syncthreads();

    constexpr int NSTEP = K / BK;
    #pragma unroll
    for (int step = 0; step < NSTEP; step++) {
        const int s = step & 1;
        if (step + 1 < NSTEP) { loadA((step + 1) * BK); loadB((step + 1) * BK); }

        #pragma unroll
        for (int ks = 0; ks < BK; ks += 16) {
            unsigned a[2][4];
            #pragma unroll
            for (int mt = 0; mt < 2; mt++) {
                int m0 = wr * 32 + mt * 16;
                a[mt][0] = *reinterpret_cast<const unsigned*>(&As[s][m0 + r4    ][ks + c2    ]);
                a[mt][1] = *reinterpret_cast<const unsigned*>(&As[s][m0 + r4 + 8][ks + c2    ]);
                a[mt][2] = *reinterpret_cast<const unsigned*>(&As[s][m0 + r4    ][ks + c2 + 8]);
                a[mt][3] = *reinterpret_cast<const unsigned*>(&As[s][m0 + r4 + 8][ks + c2 + 8]);
            }
            #pragma unroll
            for (int nt = 0; nt < NT; nt++) {
                int n0 = wc * WN + nt * 8;
                unsigned b0 = *reinterpret_cast<const unsigned*>(&Bs[s][n0 + r4][ks + c2    ]);
                unsigned b1 = *reinterpret_cast<const unsigned*>(&Bs[s][n0 + r4][ks + c2 + 8]);
                mma16816(acc[0][nt], a[0], b0, b1);
                mma16816(acc[1][nt], a[1], b0, b1);
            }
        }
        __syncthreads();
        if (step + 1 < NSTEP) {
            store(s ^ 1);
            __syncthreads();
        }
    }

    #pragma unroll
    for (int mt = 0; mt < 2; mt++) {
        int row0 = rowBase + wr * 32 + mt * 16 + r4;
        float s0 = 1.f, s8 = 1.f;
        if (DSCALE) {
            if (row0 < n)     s0 = dsc[row0];
            if (row0 + 8 < n) s8 = dsc[row0 + 8];
        }
        #pragma unroll
        for (int nt = 0; nt < NT; nt++) {
            int col = wc * WN + nt * 8 + c2;
            if (row0 < n) {
                __half2 h = __floats2half2_rn(acc[mt][nt][0] * s0, acc[mt][nt][1] * s0);
                *reinterpret_cast<unsigned*>(&out[(size_t)row0 * BN + col]) =
                    *reinterpret_cast<unsigned*>(&h);
            }
            if (row0 + 8 < n) {
                __half2 h = __floats2half2_rn(acc[mt][nt][2] * s8, acc[mt][nt][3] * s8);
                *reinterpret_cast<unsigned*>(&out[(size_t)(row0 + 8) * BN + col]) =
                    *reinterpret_cast<unsigned*>(&h);
            }
        }
    }
}

// ---------------- CSR gather-aggregate over PRE-SCALED fp16 messages ----------
// out[c] = [relu]( dinv[c] * ( sum_{r in N(c)} g[r] + g[c] ) + b ),  g = dinv⊙u
__device__ __forceinline__ void acc_add4(float4& acc, uint2 raw) {
    __half2 p0 = *reinterpret_cast<__half2*>(&raw.x);
    __half2 p1 = *reinterpret_cast<__half2*>(&raw.y);
    float2 f0 = __half22float2(p0);
    float2 f1 = __half22float2(p1);
    acc.x += f0.x; acc.y += f0.y;
    acc.z += f1.x; acc.w += f1.y;
}

template <int L, bool RELU, bool HOUT>
__global__ void aggregate_s(const int* __restrict__ rowptr, const int* __restrict__ csr,
                            const __half* __restrict__ Gh, const float* __restrict__ dinv,
                            const float4* __restrict__ bias, void* __restrict__ outv)
{
    constexpr int RS = L * 4;
    const int node = (blockIdx.x * blockDim.x + threadIdx.x) / L;
    const int lane = threadIdx.x % L;

    float4 acc = make_float4(0.f, 0.f, 0.f, 0.f);
    {   // self-loop term: g[c]
        uint2 raw = *reinterpret_cast<const uint2*>(&Gh[(size_t)node * RS + lane * 4]);
        acc_add4(acc, raw);
    }

    const int start = rowptr[node];
    const int end   = rowptr[node + 1];

    int idx = 0;
    if (start + lane < end) idx = csr[start + lane];

    for (int p = start; p < end; p += L) {
        const int m = min(L, end - p);
        int nidx = 0;
        if (p + L < end && p + L + lane < end) nidx = csr[p + L + lane];

        int j = 0;
        for (; j + 4 <= m; j += 4) {
            int r0 = __shfl_sync(0xffffffffu, idx, j + 0, L);
            int r1 = __shfl_sync(0xffffffffu, idx, j + 1, L);
            int r2 = __shfl_sync(0xffffffffu, idx, j + 2, L);
            int r3 = __shfl_sync(0xffffffffu, idx, j + 3, L);
            uint2 va = *reinterpret_cast<const uint2*>(&Gh[(size_t)r0 * RS + lane * 4]);
            uint2 vb = *reinterpret_cast<const uint2*>(&Gh[(size_t)r1 * RS + lane * 4]);
            uint2 vc = *reinterpret_cast<const uint2*>(&Gh[(size_t)r2 * RS + lane * 4]);
            uint2 vd = *reinterpret_cast<const uint2*>(&Gh[(size_t)r3 * RS + lane * 4]);
            acc_add4(acc, va);
            acc_add4(acc, vb);
            acc_add4(acc, vc);
            acc_add4(acc, vd);
        }
        for (; j < m; j++) {
            int r = __shfl_sync(0xffffffffu, idx, j, L);
            uint2 a = *reinterpret_cast<const uint2*>(&Gh[(size_t)r * RS + lane * 4]);
            acc_add4(acc, a);
        }
        idx = nidx;
    }

    const float ds = dinv[node];
    float4 bb = bias[lane];
    float4 r;
    r.x = fmaf(ds, acc.x, bb.x);
    r.y = fmaf(ds, acc.y, bb.y);
    r.z = fmaf(ds, acc.z, bb.z);
    r.w = fmaf(ds, acc.w, bb.w);
    if (RELU) {
        r.x = fmaxf(r.x, 0.f); r.y = fmaxf(r.y, 0.f);
        r.z = fmaxf(r.z, 0.f); r.w = fmaxf(r.w, 0.f);
    }
    if (HOUT) {
        __half2 h0 = __floats2half2_rn(r.x, r.y);
        __half2 h1 = __floats2half2_rn(r.z, r.w);
        uint2 o;
        o.x = *reinterpret_cast<unsigned*>(&h0);
        o.y = *reinterpret_cast<unsigned*>(&h1);
        reinterpret_cast<uint2*>(outv)[(size_t)node * L + lane] = o;
    } else {
        reinterpret_cast<float4*>(outv)[(size_t)node * L + lane] = r;
    }
}

// ---------------- launch ----------------
extern "C" void kernel_launch(void* const* d_in, const int* in_sizes, int n_in,
                              void* d_out, int out_size)
{
    const float* x  = (const float*)d_in[0];
    const int*   ei = (const int*)  d_in[1];
    const float* W1 = (const float*)d_in[2];
    const float* b1 = (const float*)d_in[3];
    const float* W2 = (const float*)d_in[4];
    const float* b2 = (const float*)d_in[5];
    float* out = (float*)d_out;

    int *degi, *rowptr, *csr;
    unsigned short* pos;
    unsigned long long* desc;
    float *dinv;
    __half *wt1, *wt2, *u1h, *h, *u2h;
    cudaGetSymbolAddress((void**)&degi,   g_degi);
    cudaGetSymbolAddress((void**)&pos,    g_pos);
    cudaGetSymbolAddress((void**)&rowptr, g_rowptr);
    cudaGetSymbolAddress((void**)&csr,    g_csr);
    cudaGetSymbolAddress((void**)&desc,   g_desc);
    cudaGetSymbolAddress((void**)&dinv,   g_dinv);
    cudaGetSymbolAddress((void**)&wt1,    g_wt1);
    cudaGetSymbolAddress((void**)&wt2,    g_wt2);
    cudaGetSymbolAddress((void**)&u1h,    g_u1h);
    cudaGetSymbolAddress((void**)&h,      g_h);
    cudaGetSymbolAddress((void**)&u2h,    g_u2h);

    static cudaStream_t s1 = nullptr;
    static cudaEvent_t  evFork = nullptr, evScan = nullptr, evJoin = nullptr;
    if (!s1) {
        cudaStreamCreateWithFlags(&s1, cudaStreamNonBlocking);
        cudaEventCreateWithFlags(&evFork, cudaEventDisableTiming);
        cudaEventCreateWithFlags(&evScan, cudaEventDisableTiming);
        cudaEventCreateWithFlags(&evJoin, cudaEventDisableTiming);
    }

    const int T = 256;

    // ---- fork immediately: CSR chain on s1 ----
    cudaEventRecord(evFork, 0);
    cudaStreamWaitEvent(s1, evFork, 0);

    cudaMemsetAsync(degi, 0, (size_t)N_NODES * sizeof(int), s1);
    cudaMemsetAsync(desc, 0, (size_t)NB_SCAN * sizeof(unsigned long long), s1);
    deg_pos4 <<<(N_EDGES / 4 + T - 1) / T, T, 0, s1>>>(
        (const int4*)(ei + N_EDGES), degi, (ushort4*)pos);
    scan_rowptr<<<NB_SCAN, 256, 0, s1>>>(degi, dinv, rowptr, desc);
    cudaEventRecord(evScan, s1);                      // dinv + rowptr ready
    csr_fill4<<<(N_EDGES / 4 + T - 1) / T, T, 0, s1>>>(
        (const int4*)ei, (const int4*)(ei + N_EDGES), (const ushort4*)pos,
        rowptr, csr);
    conv_wt2<<<(HIDIM * OUTDIM + T - 1) / T, T, 0, s1>>>(W2, wt2);
    cudaEventRecord(evJoin, s1);

    // ---- main stream: wt1 convert + GEMM1 (x converted inside tile load) ----
    conv_wt1<<<(INDIM * HIDIM + T - 1) / T, T>>>(W1, wt1);
    gemm_mma<INDIM, HIDIM, true, false>
        <<<(N_NODES + 127) / 128, 256>>>((const void*)x, wt1, u1h, N_NODES, nullptr);

    // ---- partial join: dinv ready -> scale u1h while csr_fill still runs ----
    cudaStreamWaitEvent(0, evScan, 0);
    {
        size_t n8 = (size_t)N_NODES * HIDIM / 8;
        scale_g<<<(int)((n8 + T - 1) / T), T>>>(u1h, dinv);
    }

    // ---- full join: CSR + wt2 ready ----
    cudaStreamWaitEvent(0, evJoin, 0);

    // layer 1 aggregate -> h (fp16)
    aggregate_s<32, true, true><<<N_NODES / 8, 256>>>(
        rowptr, csr, u1h, dinv, (const float4*)b1, (void*)h);

    // layer 2: GEMM2 epilogue applies dinv row-scale
    gemm_mma<HIDIM, OUTDIM, false, true>
        <<<(N_NODES + 127) / 128, 256>>>((const void*)h, wt2, u2h, N_NODES, dinv);
    aggregate_s<16, false, false><<<N_NODES / 16, 256>>>(
        rowptr, csr, u2h, dinv, (const float4*)b2, (void*)out);
}

// round 16
// speedup vs baseline: 1.0246x; 1.0246x over previous
#include <cuda_runtime.h>
#include <cuda_fp16.h>
#include <cstddef>
#include <cstdint>

#define N_NODES 50000
#define N_EDGES 1600000
#define INDIM   256
#define HIDIM   128
#define OUTDIM  64
#define NB_SCAN ((N_NODES + 256) / 256)   // 196

// ---------------- scratch (allocation-free: __device__ globals) ----------------
__device__ int            g_degi  [N_NODES];
__device__ unsigned short g_pos   [N_EDGES];   // slot within dst bucket (coalesced)
__device__ int            g_rowptr[N_NODES + 1];
__device__ int            g_csr   [N_EDGES];   // int: 4B scatter granularity
__device__ unsigned long long g_desc[NB_SCAN];
__device__ float  g_dinv  [N_NODES];
__device__ __half g_wt1   [(size_t)HIDIM * INDIM];     // W1^T fp16 [128][256]
__device__ __half g_wt2   [(size_t)OUTDIM * HIDIM];    // W2^T fp16 [64][128]
__device__ __half g_u1h   [(size_t)N_NODES * HIDIM];   // x @ W1, then dinv-scaled
__device__ __half g_h     [(size_t)N_NODES * HIDIM];   // layer1 out (fp16)
__device__ __half g_u2h   [(size_t)N_NODES * OUTDIM];  // dinv * (h @ W2) (fp16)

// ---------------- weight convert kernel (both, on main stream) ----------------
__global__ void conv_weights(const float* __restrict__ W1, __half* __restrict__ Wt1,
                             const float* __restrict__ W2, __half* __restrict__ Wt2) {
    int i = blockIdx.x * blockDim.x + threadIdx.x;
    if (i < INDIM * HIDIM) {
        int m = i / INDIM, k = i % INDIM;
        Wt1[i] = __float2half(W1[(size_t)k * HIDIM + m]);
    }
    if (i < HIDIM * OUTDIM) {
        int m = i / HIDIM, k = i % HIDIM;
        Wt2[i] = __float2half(W2[(size_t)k * OUTDIM + m]);
    }
}

// ---------------- CSR build kernels ----------------
__global__ void deg_pos4(const int4* __restrict__ col4, int* __restrict__ degi,
                         ushort4* __restrict__ pos4) {
    int i = blockIdx.x * blockDim.x + threadIdx.x;
    if (i >= N_EDGES / 4) return;
    int4 c = col4[i];
    ushort4 p;
    p.x = (unsigned short)atomicAdd(&degi[c.x], 1);
    p.y = (unsigned short)atomicAdd(&degi[c.y], 1);
    p.z = (unsigned short)atomicAdd(&degi[c.z], 1);
    p.w = (unsigned short)atomicAdd(&degi[c.w], 1);
    pos4[i] = p;
}

__global__ void scan_rowptr(const int* __restrict__ degi, float* __restrict__ dinv,
                            int* __restrict__ rowptr,
                            volatile unsigned long long* desc)
{
    __shared__ int sh[256];
    __shared__ int red[256];
    const int b = blockIdx.x, t = threadIdx.x;
    const int i = b * 256 + t;

    int v = (i < N_NODES) ? degi[i] : 0;
    if (i < N_NODES) dinv[i] = rsqrtf((float)v + 1.0f);   // +1 self loop

    sh[t] = v;
    __syncthreads();
    #pragma unroll
    for (int off = 1; off < 256; off <<= 1) {
        int x = (t >= off) ? sh[t - off] : 0;
        __syncthreads();
        sh[t] += x;
        __syncthreads();
    }
    const int incl  = sh[t];
    const int total = sh[255];

    if (t == 0) desc[b] = (1ULL << 32) | (unsigned)total;

    int contrib = 0;
    if (t < b) {
        unsigned long long d;
        do { d = desc[t]; } while ((d >> 32) == 0ULL);
        contrib = (int)(unsigned)d;
    }
    red[t] = contrib;
    __syncthreads();
    #pragma unroll
    for (int s = 128; s > 0; s >>= 1) {
        if (t < s) red[t] += red[t + s];
        __syncthreads();
    }
    const int off = red[0];

    if (i <= N_NODES) rowptr[i] = off + incl - v;
}

__global__ void csr_fill4(const int4* __restrict__ row4, const int4* __restrict__ col4,
                          const ushort4* __restrict__ pos4,
                          const int* __restrict__ rowptr, int* __restrict__ csr) {
    int i = blockIdx.x * blockDim.x + threadIdx.x;
    if (i >= N_EDGES / 4) return;
    int4 r = row4[i];
    int4 c = col4[i];
    ushort4 p = pos4[i];
    int b0 = __ldg(&rowptr[c.x]);
    int b1 = __ldg(&rowptr[c.y]);
    int b2 = __ldg(&rowptr[c.z]);
    int b3 = __ldg(&rowptr[c.w]);
    csr[b0 + p.x] = r.x;
    csr[b1 + p.y] = r.y;
    csr[b2 + p.z] = r.z;
    csr[b3 + p.w] = r.w;
}

// ---------------- scale messages: g[row,:] *= dinv[row]  (fp16, in place) -----
__global__ void scale_g(__half* __restrict__ G, const float* __restrict__ dinv) {
    size_t i = (size_t)blockIdx.x * blockDim.x + threadIdx.x;
    constexpr size_t N8 = (size_t)N_NODES * HIDIM / 8;   // uint4 = 8 halves
    if (i >= N8) return;
    int row = (int)(i / (HIDIM / 8));
    float s = dinv[row];
    uint4 raw = reinterpret_cast<uint4*>(G)[i];
    __half2 p0 = *reinterpret_cast<__half2*>(&raw.x);
    __half2 p1 = *reinterpret_cast<__half2*>(&raw.y);
    __half2 p2 = *reinterpret_cast<__half2*>(&raw.z);
    __half2 p3 = *reinterpret_cast<__half2*>(&raw.w);
    float2 f0 = __half22float2(p0), f1 = __half22float2(p1);
    float2 f2 = __half22float2(p2), f3 = __half22float2(p3);
    p0 = __floats2half2_rn(f0.x * s, f0.y * s);
    p1 = __floats2half2_rn(f1.x * s, f1.y * s);
    p2 = __floats2half2_rn(f2.x * s, f2.y * s);
    p3 = __floats2half2_rn(f3.x * s, f3.y * s);
    raw.x = *reinterpret_cast<unsigned*>(&p0);
    raw.y = *reinterpret_cast<unsigned*>(&p1);
    raw.z = *reinterpret_cast<unsigned*>(&p2);
    raw.w = *reinterpret_cast<unsigned*>(&p3);
    reinterpret_cast<uint4*>(G)[i] = raw;
}

// ---------------- tensor-core fp16 GEMM: out = [dinv⊙](A @ Bt^T) ----------------
__device__ __forceinline__ void mma16816(float* c, const unsigned* a,
                                         unsigned b0, unsigned b1) {
    asm volatile(
        "mma.sync.aligned.m16n8k16.row.col.f32.f16.f16.f32 "
        "{%0,%1,%2,%3}, {%4,%5,%6,%7}, {%8,%9}, {%0,%1,%2,%3};"
        : "+f"(c[0]), "+f"(c[1]), "+f"(c[2]), "+f"(c[3])
        : "r"(a[0]), "r"(a[1]), "r"(a[2]), "r"(a[3]), "r"(b0), "r"(b1));
}

template <int K, int BN, bool AF32, bool DSCALE>
__global__ void __launch_bounds__(256)
gemm_mma(const void* __restrict__ Av, const __half* __restrict__ Bt,
         __half* __restrict__ out, int n, const float* __restrict__ dsc)
{
    constexpr int BM  = 128;
    constexpr int BK  = 32;
    constexpr int PAD = 40;
    constexpr int WN  = BN / 2;
    constexpr int NT  = WN / 8;
    constexpr int AL  = (BM * 8) / 256;
    constexpr int BL  = (BN * 8) / 256;

    __shared__ __half As[2][BM][PAD];
    __shared__ __half Bs[2][BN][PAD];

    const int tid  = threadIdx.x;
    const int lane = tid & 31;
    const int wid  = tid >> 5;
    const int wr   = wid & 3;
    const int wc   = wid >> 2;
    const int rowBase = blockIdx.x * BM;

    const int r4 = lane >> 2;
    const int c2 = (lane & 3) * 2;

    float acc[2][NT][4];
    #pragma unroll
    for (int mt = 0; mt < 2; mt++)
        #pragma unroll
        for (int nt = 0; nt < NT; nt++)
            #pragma unroll
            for (int q = 0; q < 4; q++) acc[mt][nt][q] = 0.f;

    uint2 abuf[AL], bbuf[BL];

    auto loadA = [&](int k0) {
        #pragma unroll
        for (int i = 0; i < AL; i++) {
            int idx = tid + i * 256;
            int r = idx >> 3, sg = idx & 7;
            int gr = rowBase + r;
            uint2 v = make_uint2(0u, 0u);
            if (gr < n) {
                if (AF32) {
                    float4 f = *reinterpret_cast<const float4*>(
                        (const float*)Av + (size_t)gr * K + k0 + sg * 4);
                    __half2 h0 = __floats2half2_rn(f.x, f.y);
                    __half2 h1 = __floats2half2_rn(f.z, f.w);
                    v.x = *reinterpret_cast<unsigned*>(&h0);
                    v.y = *reinterpret_cast<unsigned*>(&h1);
                } else {
                    v = *reinterpret_cast<const uint2*>(
                        (const __half*)Av + (size_t)gr * K + k0 + sg * 4);
                }
            }
            abuf[i] = v;
        }
    };
    auto loadB = [&](int k0) {
        #pragma unroll
        for (int i = 0; i < BL; i++) {
            int idx = tid + i * 256;
            int r = idx >> 3, sg = idx & 7;
            bbuf[i] = *reinterpret_cast<const uint2*>(&Bt[(size_t)r * K + k0 + sg * 4]);
        }
    };
    auto store = [&](int s) {
        #pragma unroll
        for (int i = 0; i < AL; i++) {
            int idx = tid + i * 256;
            int r = idx >> 3, sg = idx & 7;
            *reinterpret_cast<uint2*>(&As[s][r][sg * 4]) = abuf[i];
        }
        #pragma unroll
        for (int i = 0; i < BL; i++) {
            int idx = tid + i * 256;
            int r = idx >> 3, sg = idx & 7;
            *reinterpret_cast<uint2*>(&Bs[s][r][sg * 4]) = bbuf[i];
        }
    };

    loadA(0); loadB(0);
    store(0);
    __syncthreads();

    constexpr int NSTEP = K / BK;
    #pragma unroll
    for (int step = 0; step < NSTEP; step++) {
        const int s = step & 1;
        if (step + 1 < NSTEP) { loadA((step + 1) * BK); loadB((step + 1) * BK); }

        #pragma unroll
        for (int ks = 0; ks < BK; ks += 16) {
            unsigned a[2][4];
            #pragma unroll
            for (int mt = 0; mt < 2; mt++) {
                int m0 = wr * 32 + mt * 16;
                a[mt][0] = *reinterpret_cast<const unsigned*>(&As[s][m0 + r4    ][ks + c2    ]);
                a[mt][1] = *reinterpret_cast<const unsigned*>(&As[s][m0 + r4 + 8][ks + c2    ]);
                a[mt][2] = *reinterpret_cast<const unsigned*>(&As[s][m0 + r4    ][ks + c2 + 8]);
                a[mt][3] = *reinterpret_cast<const unsigned*>(&As[s][m0 + r4 + 8][ks + c2 + 8]);
            }
            #pragma unroll
            for (int nt = 0; nt < NT; nt++) {
                int n0 = wc * WN + nt * 8;
                unsigned b0 = *reinterpret_cast<const unsigned*>(&Bs[s][n0 + r4][ks + c2    ]);
                unsigned b1 = *reinterpret_cast<const unsigned*>(&Bs[s][n0 + r4][ks + c2 + 8]);
                mma16816(acc[0][nt], a[0], b0, b1);
                mma16816(acc[1][nt], a[1], b0, b1);
            }
        }
        __syncthreads();
        if (step + 1 < NSTEP) {
            store(s ^ 1);
            __syncthreads();
        }
    }

    #pragma unroll
    for (int mt = 0; mt < 2; mt++) {
        int row0 = rowBase + wr * 32 + mt * 16 + r4;
        float s0 = 1.f, s8 = 1.f;
        if (DSCALE) {
            if (row0 < n)     s0 = dsc[row0];
            if (row0 + 8 < n) s8 = dsc[row0 + 8];
        }
        #pragma unroll
        for (int nt = 0; nt < NT; nt++) {
            int col = wc * WN + nt * 8 + c2;
            if (row0 < n) {
                __half2 h = __floats2half2_rn(acc[mt][nt][0] * s0, acc[mt][nt][1] * s0);
                *reinterpret_cast<unsigned*>(&out[(size_t)row0 * BN + col]) =
                    *reinterpret_cast<unsigned*>(&h);
            }
            if (row0 + 8 < n) {
                __half2 h = __floats2half2_rn(acc[mt][nt][2] * s8, acc[mt][nt][3] * s8);
                *reinterpret_cast<unsigned*>(&out[(size_t)(row0 + 8) * BN + col]) =
                    *reinterpret_cast<unsigned*>(&h);
            }
        }
    }
}

// ---------------- CSR gather-aggregate over PRE-SCALED fp16 messages ----------
// out[c] = [relu]( dinv[c] * ( sum_{r in N(c)} g[r] + g[c] ) + b ),  g = dinv⊙u
__device__ __forceinline__ void acc_add4(float4& acc, uint2 raw) {
    __half2 p0 = *reinterpret_cast<__half2*>(&raw.x);
    __half2 p1 = *reinterpret_cast<__half2*>(&raw.y);
    float2 f0 = __half22float2(p0);
    float2 f1 = __half22float2(p1);
    acc.x += f0.x; acc.y += f0.y;
    acc.z += f1.x; acc.w += f1.y;
}

template <int L, bool RELU, bool HOUT>
__global__ void aggregate_s(const int* __restrict__ rowptr, const int* __restrict__ csr,
                            const __half* __restrict__ Gh, const float* __restrict__ dinv,
                            const float4* __restrict__ bias, void* __restrict__ outv)
{
    constexpr int RS = L * 4;
    const int node = (blockIdx.x * blockDim.x + threadIdx.x) / L;
    const int lane = threadIdx.x % L;

    float4 acc = make_float4(0.f, 0.f, 0.f, 0.f);
    {   // self-loop term: g[c]
        uint2 raw = *reinterpret_cast<const uint2*>(&Gh[(size_t)node * RS + lane * 4]);
        acc_add4(acc, raw);
    }

    const int start = rowptr[node];
    const int end   = rowptr[node + 1];

    int idx = 0;
    if (start + lane < end) idx = csr[start + lane];

    for (int p = start; p < end; p += L) {
        const int m = min(L, end - p);
        int nidx = 0;
        if (p + L < end && p + L + lane < end) nidx = csr[p + L + lane];

        int j = 0;
        for (; j + 4 <= m; j += 4) {
            int r0 = __shfl_sync(0xffffffffu, idx, j + 0, L);
            int r1 = __shfl_sync(0xffffffffu, idx, j + 1, L);
            int r2 = __shfl_sync(0xffffffffu, idx, j + 2, L);
            int r3 = __shfl_sync(0xffffffffu, idx, j + 3, L);
            uint2 va = *reinterpret_cast<const uint2*>(&Gh[(size_t)r0 * RS + lane * 4]);
            uint2 vb = *reinterpret_cast<const uint2*>(&Gh[(size_t)r1 * RS + lane * 4]);
            uint2 vc = *reinterpret_cast<const uint2*>(&Gh[(size_t)r2 * RS + lane * 4]);
            uint2 vd = *reinterpret_cast<const uint2*>(&Gh[(size_t)r3 * RS + lane * 4]);
            acc_add4(acc, va);
            acc_add4(acc, vb);
            acc_add4(acc, vc);
            acc_add4(acc, vd);
        }
        for (; j < m; j++) {
            int r = __shfl_sync(0xffffffffu, idx, j, L);
            uint2 a = *reinterpret_cast<const uint2*>(&Gh[(size_t)r * RS + lane * 4]);
            acc_add4(acc, a);
        }
        idx = nidx;
    }

    const float ds = dinv[node];
    float4 bb = bias[lane];
    float4 r;
    r.x = fmaf(ds, acc.x, bb.x);
    r.y = fmaf(ds, acc.y, bb.y);
    r.z = fmaf(ds, acc.z, bb.z);
    r.w = fmaf(ds, acc.w, bb.w);
    if (RELU) {
        r.x = fmaxf(r.x, 0.f); r.y = fmaxf(r.y, 0.f);
        r.z = fmaxf(r.z, 0.f); r.w = fmaxf(r.w, 0.f);
    }
    if (HOUT) {
        __half2 h0 = __floats2half2_rn(r.x, r.y);
        __half2 h1 = __floats2half2_rn(r.z, r.w);
        uint2 o;
        o.x = *reinterpret_cast<unsigned*>(&h0);
        o.y = *reinterpret_cast<unsigned*>(&h1);
        reinterpret_cast<uint2*>(outv)[(size_t)node * L + lane] = o;
    } else {
        reinterpret_cast<float4*>(outv)[(size_t)node * L + lane] = r;
    }
}

// ---------------- launch ----------------
extern "C" void kernel_launch(void* const* d_in, const int* in_sizes, int n_in,
                              void* d_out, int out_size)
{
    const float* x  = (const float*)d_in[0];
    const int*   ei = (const int*)  d_in[1];
    const float* W1 = (const float*)d_in[2];
    const float* b1 = (const float*)d_in[3];
    const float* W2 = (const float*)d_in[4];
    const float* b2 = (const float*)d_in[5];
    float* out = (float*)d_out;

    int *degi, *rowptr, *csr;
    unsigned short* pos;
    unsigned long long* desc;
    float *dinv;
    __half *wt1, *wt2, *u1h, *h, *u2h;
    cudaGetSymbolAddress((void**)&degi,   g_degi);
    cudaGetSymbolAddress((void**)&pos,    g_pos);
    cudaGetSymbolAddress((void**)&rowptr, g_rowptr);
    cudaGetSymbolAddress((void**)&csr,    g_csr);
    cudaGetSymbolAddress((void**)&desc,   g_desc);
    cudaGetSymbolAddress((void**)&dinv,   g_dinv);
    cudaGetSymbolAddress((void**)&wt1,    g_wt1);
    cudaGetSymbolAddress((void**)&wt2,    g_wt2);
    cudaGetSymbolAddress((void**)&u1h,    g_u1h);
    cudaGetSymbolAddress((void**)&h,      g_h);
    cudaGetSymbolAddress((void**)&u2h,    g_u2h);

    static cudaStream_t s1 = nullptr;
    static cudaEvent_t  evFork = nullptr, evScan = nullptr, evJoin = nullptr;
    if (!s1) {
        cudaStreamCreateWithFlags(&s1, cudaStreamNonBlocking);
        cudaEventCreateWithFlags(&evFork, cudaEventDisableTiming);
        cudaEventCreateWithFlags(&evScan, cudaEventDisableTiming);
        cudaEventCreateWithFlags(&evJoin, cudaEventDisableTiming);
    }

    const int T = 256;

    // ---- fork immediately: CSR chain on s1 ----
    cudaEventRecord(evFork, 0);
    cudaStreamWaitEvent(s1, evFork, 0);

    cudaMemsetAsync(degi, 0, (size_t)N_NODES * sizeof(int), s1);
    cudaMemsetAsync(desc, 0, (size_t)NB_SCAN * sizeof(unsigned long long), s1);
    deg_pos4 <<<(N_EDGES / 4 + T - 1) / T, T, 0, s1>>>(
        (const int4*)(ei + N_EDGES), degi, (ushort4*)pos);
    scan_rowptr<<<NB_SCAN, 256, 0, s1>>>(degi, dinv, rowptr, desc);
    cudaEventRecord(evScan, s1);                      // dinv + rowptr ready
    csr_fill4<<<(N_EDGES / 4 + T - 1) / T, T, 0, s1>>>(
        (const int4*)ei, (const int4*)(ei + N_EDGES), (const ushort4*)pos,
        rowptr, csr);
    cudaEventRecord(evJoin, s1);

    // ---- main stream: weight convert + GEMM1 (x converted inside tile load) ----
    conv_weights<<<(INDIM * HIDIM + T - 1) / T, T>>>(W1, wt1, W2, wt2);
    gemm_mma<INDIM, HIDIM, true, false>
        <<<(N_NODES + 127) / 128, 256>>>((const void*)x, wt1, u1h, N_NODES, nullptr);

    // ---- partial join: dinv ready -> scale u1h overlapping csr_fill's tail ----
    cudaStreamWaitEvent(0, evScan, 0);
    {
        size_t n8 = (size_t)N_NODES * HIDIM / 8;
        scale_g<<<(int)((n8 + T - 1) / T), T>>>(u1h, dinv);
    }

    // ---- full join: CSR ready ----
    cudaStreamWaitEvent(0, evJoin, 0);

    // layer 1 aggregate -> h (fp16)
    aggregate_s<32, true, true><<<N_NODES / 8, 256>>>(
        rowptr, csr, u1h, dinv, (const float4*)b1, (void*)h);

    // layer 2: GEMM2 epilogue applies dinv row-scale
    gemm_mma<HIDIM, OUTDIM, false, true>
        <<<(N_NODES + 127) / 128, 256>>>((const void*)h, wt2, u2h, N_NODES, dinv);
    aggregate_s<16, false, false><<<N_NODES / 16, 256>>>(
        rowptr, csr, u2h, dinv, (const float4*)b2, (void*)out);
}